// round 5
// baseline (speedup 1.0000x reference)
#include <cuda_runtime.h>
#include <cuda_bf16.h>
#include <math.h>
#include <stdint.h>

// ---------------- problem constants ----------------
#define B_      16
#define S_      576
#define F_      700
#define FP_     704             // F padded to mult of 32
#define D_      64
#define KC_     1024
#define T_      (B_*S_)         // 9216 tokens
#define H1_     512
#define H2_     256
#define ENC_    128             // 2*D
#define SF_     (S_*F_)         // 403200
#define SD_     (S_*D_)         // 36864
#define ZSPLIT  2

#define OUT_REC  0
#define OUT_MEAN (B_*SF_)
#define OUT_LV   (OUT_MEAN + T_*D_)
#define OUT_VQL  (OUT_LV + T_*D_)

#define DEC1_CHUNKS 144

typedef unsigned long long u64;
typedef __nv_bfloat16 bf16;

// ---------------- scratch (device globals; no allocation allowed) ----------------
__device__ __align__(256) bf16  g_xh[T_*FP_];
__device__ __align__(256) bf16  g_xl[T_*FP_];
__device__ __align__(256) bf16  g_w1h[H1_*FP_];
__device__ __align__(256) bf16  g_w1l[H1_*FP_];
__device__ __align__(256) bf16  g_w2h[H2_*H1_];
__device__ __align__(256) bf16  g_w2l[H2_*H1_];
__device__ __align__(256) bf16  g_w3h[ENC_*H2_];
__device__ __align__(256) bf16  g_w3l[ENC_*H2_];
__device__ __align__(256) bf16  g_h1h[T_*H1_];
__device__ __align__(256) bf16  g_h1l[T_*H1_];
__device__ __align__(256) bf16  g_h2h[T_*H2_];
__device__ __align__(256) bf16  g_h2l[T_*H2_];
__device__ __align__(256) bf16  g_zeh[T_*D_];
__device__ __align__(256) bf16  g_zel[T_*D_];
__device__ __align__(256) bf16  g_cbh[KC_*D_];
__device__ __align__(256) bf16  g_cbl[KC_*D_];
__device__ __align__(256) float g_encp[ZSPLIT*T_*ENC_];
__device__ __align__(256) float g_ze[T_*D_];
__device__ __align__(256) float g_zq[T_*D_];
__device__ __align__(256) float g_cross[T_*KC_];
__device__ __align__(256) float g_csq[KC_];
__device__ __align__(256) float g_tokloss[T_];
__device__ __align__(256) float g_dpart[DEC1_CHUNKS*16*H2_];
__device__ __align__(256) float g_dvec[16*H2_];

// ---------------- f32x2 helpers (decoder kernels) ----------------
__device__ __forceinline__ u64 dupf(float a) {
    unsigned r = __float_as_uint(a);
    u64 d;
    asm("mov.b64 %0, {%1, %1};" : "=l"(d) : "r"(r));
    return d;
}
__device__ __forceinline__ void ffma2(u64 &d, u64 a, u64 b) {
    asm("fma.rn.f32x2 %0, %1, %2, %0;" : "+l"(d) : "l"(a), "l"(b));
}
__device__ __forceinline__ float2 unpk(u64 v) {
    unsigned lo, hi;
    asm("mov.b64 {%0, %1}, %2;" : "=r"(lo), "=r"(hi) : "l"(v));
    return make_float2(__uint_as_float(lo), __uint_as_float(hi));
}
__device__ __forceinline__ float softplusf(float x) {
    return fmaxf(x, 0.0f) + log1pf(expf(-fabsf(x)));
}

// ---------------- bf16 split helpers ----------------
__device__ __forceinline__ void split2u(float x, float y, uint32_t &hi, uint32_t &lo) {
    __nv_bfloat162 h = __floats2bfloat162_rn(x, y);
    float hx = __bfloat162float(h.x), hy = __bfloat162float(h.y);
    __nv_bfloat162 l = __floats2bfloat162_rn(x - hx, y - hy);
    hi = *reinterpret_cast<uint32_t*>(&h);
    lo = *reinterpret_cast<uint32_t*>(&l);
}

// ---------------- mma.sync helpers ----------------
__device__ __forceinline__ uint32_t smem_u32(const void* p) {
    uint32_t a;
    asm("{ .reg .u64 t; cvta.to.shared.u64 t, %1; cvt.u32.u64 %0, t; }" : "=r"(a) : "l"(p));
    return a;
}
__device__ __forceinline__ void ldsm4(uint32_t (&r)[4], uint32_t addr) {
    asm volatile("ldmatrix.sync.aligned.m8n8.x4.shared.b16 {%0,%1,%2,%3}, [%4];"
                 : "=r"(r[0]), "=r"(r[1]), "=r"(r[2]), "=r"(r[3]) : "r"(addr));
}
__device__ __forceinline__ void mma_bf16(float (&d)[4], const uint32_t (&a)[4],
                                         uint32_t b0, uint32_t b1) {
    asm volatile("mma.sync.aligned.m16n8k16.row.col.f32.bf16.bf16.f32 "
                 "{%0,%1,%2,%3}, {%4,%5,%6,%7}, {%8,%9}, {%0,%1,%2,%3};"
                 : "+f"(d[0]), "+f"(d[1]), "+f"(d[2]), "+f"(d[3])
                 : "r"(a[0]), "r"(a[1]), "r"(a[2]), "r"(a[3]), "r"(b0), "r"(b1));
}

// SMEM per stage (bf16 elems): Ah [128][40] (5120) | Al +5120 | Bh +10240 | Bl +15360
#define STAGE_E   20480
#define SMEM_BYTES (2 * STAGE_E * 2)

// ---------------- bf16x3 tensor-core GEMM, pre-split operands --------------------
// C = act(A(MxK) * Bt(NxK)^T [+ bias]) with A = Ah+Al, B = Bh+Bl (bf16 pairs).
// K must be a multiple of 32 (zero-padded buffers). BM=BN=128, BK=32, 256 thr.
// MODE 1: relu + bias, output split bf16 (Ch, Cl)
// MODE 2: split-K raw fp32 partials at Cf + z*M*N
// MODE 3: fp32, no bias (Cf)
template<int MODE>
__global__ __launch_bounds__(256, 1) void mma_gemm_bf(
    int M, int N, int K, int kPerZ,
    const bf16* __restrict__ Ah, const bf16* __restrict__ Al,
    const bf16* __restrict__ Bh, const bf16* __restrict__ Bl,
    const float* __restrict__ bias,
    float* __restrict__ Cf, bf16* __restrict__ Ch, bf16* __restrict__ Cl)
{
    extern __shared__ __align__(16) bf16 sm[];
    const int tid  = threadIdx.x;
    const int wid  = tid >> 5;
    const int lane = tid & 31;
    const int row0 = blockIdx.y * 128;
    const int col0 = blockIdx.x * 128;
    const int kStart = (MODE == 2) ? blockIdx.z * kPerZ : 0;
    const int kLen   = (MODE == 2) ? kPerZ : K;
    const int NS = kLen >> 5;
    const uint32_t smb = smem_u32(sm);

    float acc[2][8][4];
#pragma unroll
    for (int mt = 0; mt < 2; ++mt)
#pragma unroll
        for (int nt = 0; nt < 8; ++nt)
#pragma unroll
            for (int q = 0; q < 4; ++q) acc[mt][nt][q] = 0.0f;

    const int lrow = tid >> 1;            // 0..127
    const int lcs  = (tid & 1) * 16;      // elem offset in BK=32

    uint4 pah[2], pal[2], pbh[2], pbl[2];

    const size_t aBase = (size_t)(row0 + lrow) * K + lcs;
    const size_t bBase = (size_t)(col0 + lrow) * K + lcs;

    // prefetch stage 0
    {
        int k0 = kStart;
        pah[0] = *(const uint4*)(Ah + aBase + k0); pah[1] = *(const uint4*)(Ah + aBase + k0 + 8);
        pal[0] = *(const uint4*)(Al + aBase + k0); pal[1] = *(const uint4*)(Al + aBase + k0 + 8);
        pbh[0] = *(const uint4*)(Bh + bBase + k0); pbh[1] = *(const uint4*)(Bh + bBase + k0 + 8);
        pbl[0] = *(const uint4*)(Bl + bBase + k0); pbl[1] = *(const uint4*)(Bl + bBase + k0 + 8);
    }
    // store stage 0
    {
        uint32_t off = lrow * 40 + lcs;
        *(uint4*)&sm[off]           = pah[0]; *(uint4*)&sm[off + 8]           = pah[1];
        *(uint4*)&sm[off + 5120]    = pal[0]; *(uint4*)&sm[off + 5120 + 8]    = pal[1];
        *(uint4*)&sm[off + 10240]   = pbh[0]; *(uint4*)&sm[off + 10240 + 8]   = pbh[1];
        *(uint4*)&sm[off + 15360]   = pbl[0]; *(uint4*)&sm[off + 15360 + 8]   = pbl[1];
    }
    __syncthreads();

    const int wm = wid >> 1, wn = wid & 1;
    const int arow  = wm * 32 + (lane & 15);
    const int acolB = (lane >> 4) * 16;
    const int brow  = wn * 64 + ((lane >> 4) << 3) + (lane & 7);
    const int bkhB  = ((lane >> 3) & 1) * 16;

    for (int s = 0; s < NS; ++s) {
        if (s + 1 < NS) {
            int k0 = kStart + (s + 1) * 32;
            pah[0] = *(const uint4*)(Ah + aBase + k0); pah[1] = *(const uint4*)(Ah + aBase + k0 + 8);
            pal[0] = *(const uint4*)(Al + aBase + k0); pal[1] = *(const uint4*)(Al + aBase + k0 + 8);
            pbh[0] = *(const uint4*)(Bh + bBase + k0); pbh[1] = *(const uint4*)(Bh + bBase + k0 + 8);
            pbl[0] = *(const uint4*)(Bl + bBase + k0); pbl[1] = *(const uint4*)(Bl + bBase + k0 + 8);
        }

        const uint32_t stgB = (uint32_t)(s & 1) * (STAGE_E * 2);
#pragma unroll
        for (int ks = 0; ks < 2; ++ks) {
            uint32_t ah[2][4], al[2][4];
#pragma unroll
            for (int mt = 0; mt < 2; ++mt) {
                uint32_t addr = smb + stgB + (uint32_t)(arow + mt * 16) * 80u
                              + (uint32_t)ks * 32u + acolB;
                ldsm4(ah[mt], addr);
                ldsm4(al[mt], addr + 10240u);
            }
            uint32_t bh[8][2], bl[8][2];
#pragma unroll
            for (int p = 0; p < 4; ++p) {
                uint32_t addr = smb + stgB + 20480u + (uint32_t)(brow + p * 16) * 80u
                              + (uint32_t)ks * 32u + bkhB;
                uint32_t r[4];
                ldsm4(r, addr);
                bh[2*p][0] = r[0]; bh[2*p][1] = r[1];
                bh[2*p+1][0] = r[2]; bh[2*p+1][1] = r[3];
                ldsm4(r, addr + 10240u);
                bl[2*p][0] = r[0]; bl[2*p][1] = r[1];
                bl[2*p+1][0] = r[2]; bl[2*p+1][1] = r[3];
            }
#pragma unroll
            for (int mt = 0; mt < 2; ++mt)
#pragma unroll
                for (int nt = 0; nt < 8; ++nt) {
                    mma_bf16(acc[mt][nt], ah[mt], bh[nt][0], bh[nt][1]);
                    mma_bf16(acc[mt][nt], ah[mt], bl[nt][0], bl[nt][1]);
                    mma_bf16(acc[mt][nt], al[mt], bh[nt][0], bh[nt][1]);
                }
        }

        if (s + 1 < NS) {
            __syncthreads();
            uint32_t off = (uint32_t)((s + 1) & 1) * STAGE_E + lrow * 40 + lcs;
            *(uint4*)&sm[off]           = pah[0]; *(uint4*)&sm[off + 8]           = pah[1];
            *(uint4*)&sm[off + 5120]    = pal[0]; *(uint4*)&sm[off + 5120 + 8]    = pal[1];
            *(uint4*)&sm[off + 10240]   = pbh[0]; *(uint4*)&sm[off + 10240 + 8]   = pbh[1];
            *(uint4*)&sm[off + 15360]   = pbl[0]; *(uint4*)&sm[off + 15360 + 8]   = pbl[1];
            __syncthreads();
        }
    }

    // ---- epilogue ----
#pragma unroll
    for (int mt = 0; mt < 2; ++mt) {
        int r = row0 + wm * 32 + mt * 16 + (lane >> 2);
#pragma unroll
        for (int nt = 0; nt < 8; ++nt) {
            int c = col0 + wn * 64 + nt * 8 + (lane & 3) * 2;
            if (MODE == 1) {
                float b0 = bias[c], b1 = bias[c + 1];
                float v0 = fmaxf(acc[mt][nt][0] + b0, 0.0f);
                float v1 = fmaxf(acc[mt][nt][1] + b1, 0.0f);
                float v2 = fmaxf(acc[mt][nt][2] + b0, 0.0f);
                float v3 = fmaxf(acc[mt][nt][3] + b1, 0.0f);
                uint32_t h, l;
                split2u(v0, v1, h, l);
                *(uint32_t*)&Ch[(size_t)r * N + c] = h;
                *(uint32_t*)&Cl[(size_t)r * N + c] = l;
                split2u(v2, v3, h, l);
                *(uint32_t*)&Ch[(size_t)(r + 8) * N + c] = h;
                *(uint32_t*)&Cl[(size_t)(r + 8) * N + c] = l;
            } else if (MODE == 2) {
                float* Co = Cf + (size_t)blockIdx.z * M * N;
                *(float2*)&Co[(size_t)r * N + c]       = make_float2(acc[mt][nt][0], acc[mt][nt][1]);
                *(float2*)&Co[(size_t)(r + 8) * N + c] = make_float2(acc[mt][nt][2], acc[mt][nt][3]);
            } else {
                *(float2*)&Cf[(size_t)r * N + c]       = make_float2(acc[mt][nt][0], acc[mt][nt][1]);
                *(float2*)&Cf[(size_t)(r + 8) * N + c] = make_float2(acc[mt][nt][2], acc[mt][nt][3]);
            }
        }
    }
}

// ---------------- transpose + split: Wt{h,l}[n][kp] = split(W[k][n]), zero-pad ----
__global__ void transpose_split_kernel(const float* __restrict__ W,
                                       bf16* __restrict__ Wth, bf16* __restrict__ Wtl,
                                       int K, int N, int KP)
{
    __shared__ float tile[32][33];
    int kb = blockIdx.y * 32, nb = blockIdx.x * 32;
    int tx = threadIdx.x, ty = threadIdx.y;   // 32 x 8
#pragma unroll
    for (int i = 0; i < 32; i += 8) {
        int k = kb + ty + i, n = nb + tx;
        tile[ty + i][tx] = (k < K && n < N) ? W[(size_t)k * N + n] : 0.0f;
    }
    __syncthreads();
#pragma unroll
    for (int i = 0; i < 32; i += 8) {
        int n = nb + ty + i, k = kb + tx;
        if (n < N && k < KP) {
            float v = tile[tx][ty + i];
            bf16 h = __float2bfloat16(v);
            Wth[(size_t)n * KP + k] = h;
            Wtl[(size_t)n * KP + k] = __float2bfloat16(v - __bfloat162float(h));
        }
    }
}

// ---------------- split x into padded bf16 hi/lo ----------------
__global__ void split_x_kernel(const float* __restrict__ x) {
    int idx = blockIdx.x * 256 + threadIdx.x;       // one per 4 elems of padded row
    if (idx >= T_ * (FP_ / 4)) return;
    int t  = idx / (FP_ / 4);
    int c4 = (idx % (FP_ / 4)) * 4;
    float4 v = make_float4(0.f, 0.f, 0.f, 0.f);
    if (c4 < F_) v = *(const float4*)(x + (size_t)t * F_ + c4);
    uint32_t h01, l01, h23, l23;
    split2u(v.x, v.y, h01, l01);
    split2u(v.z, v.w, h23, l23);
    *(uint2*)&g_xh[(size_t)t * FP_ + c4] = make_uint2(h01, h23);
    *(uint2*)&g_xl[(size_t)t * FP_ + c4] = make_uint2(l01, l23);
}

// ---------------- codebook split + squared norms (warp per code) ----------------
__global__ void cb_prep_kernel(const float* __restrict__ cb) {
    int w    = (blockIdx.x * 256 + threadIdx.x) >> 5;   // 0..1023, grid 128
    int lane = threadIdx.x & 31;
    float2 v = *(const float2*)(cb + (size_t)w * 64 + lane * 2);
    float s = v.x * v.x + v.y * v.y;
#pragma unroll
    for (int off = 16; off; off >>= 1) s += __shfl_down_sync(0xffffffffu, s, off);
    uint32_t h, l;
    split2u(v.x, v.y, h, l);
    *(uint32_t*)&g_cbh[(size_t)w * 64 + lane * 2] = h;
    *(uint32_t*)&g_cbl[(size_t)w * 64 + lane * 2] = l;
    if (lane == 0) g_csq[w] = s;
}

// ---------------- combine enc partials + reparameterize + split z_e ----------------
__global__ void reparam_kernel(const float* __restrict__ eps,
                               const float* __restrict__ be3,
                               float* __restrict__ out) {
    int i = blockIdx.x * 256 + threadIdx.x;
    if (i >= T_ * D_) return;
    int t = i >> 6, d = i & 63;
    float m  = be3[d]      + g_encp[t * ENC_ + d]      + g_encp[T_*ENC_ + t * ENC_ + d];
    float lv = be3[64 + d] + g_encp[t * ENC_ + 64 + d] + g_encp[T_*ENC_ + t * ENC_ + 64 + d];
    float zv = m + expf(0.5f * lv) * eps[i];
    g_ze[i] = zv;
    bf16 zh = __float2bfloat16(zv);
    g_zeh[i] = zh;
    g_zel[i] = __float2bfloat16(zv - __bfloat162float(zh));
    out[OUT_MEAN + i] = m;
    out[OUT_LV + i]   = lv;
}

// warp per token: argmin over 1024 codes of (c_sq - 2*cross), gather, per-token loss
__global__ __launch_bounds__(256) void argmin_kernel(const float* __restrict__ cb) {
    int t    = (blockIdx.x * 256 + threadIdx.x) >> 5;
    int lane = threadIdx.x & 31;

    const float4* cr = (const float4*)g_cross + (size_t)t * 256;
    const float4* cq = (const float4*)g_csq;

    float best = 3.4e38f;
    int bestk = 0;
#pragma unroll
    for (int i = 0; i < 8; ++i) {
        int v = lane + i * 32;
        float4 c = cr[v];
        float4 q = cq[v];
        float s0 = q.x - 2.0f * c.x;
        float s1 = q.y - 2.0f * c.y;
        float s2 = q.z - 2.0f * c.z;
        float s3 = q.w - 2.0f * c.w;
        int kb = v * 4;
        if (s0 < best) { best = s0; bestk = kb;     }
        if (s1 < best) { best = s1; bestk = kb + 1; }
        if (s2 < best) { best = s2; bestk = kb + 2; }
        if (s3 < best) { best = s3; bestk = kb + 3; }
    }
#pragma unroll
    for (int off = 16; off; off >>= 1) {
        float ob = __shfl_down_sync(0xffffffffu, best, off);
        int   ok = __shfl_down_sync(0xffffffffu, bestk, off);
        if (ob < best || (ob == best && ok < bestk)) { best = ob; bestk = ok; }
    }
    bestk = __shfl_sync(0xffffffffu, bestk, 0);

    float l = 0.0f;
    if (lane < 16) {
        float4 cv = ((const float4*)cb)[bestk * 16 + lane];
        float4 zv = ((const float4*)g_ze)[t * 16 + lane];
        ((float4*)g_zq)[t * 16 + lane] = cv;
        float dx = zv.x - cv.x, dy = zv.y - cv.y;
        float dz = zv.z - cv.z, dw = zv.w - cv.w;
        l = dx * dx + dy * dy + dz * dz + dw * dw;
    }
#pragma unroll
    for (int off = 16; off; off >>= 1)
        l += __shfl_down_sync(0xffffffffu, l, off);
    if (lane == 0) g_tokloss[t] = l;
}

__global__ __launch_bounds__(256) void dec1_part_kernel(const float* __restrict__ W) {
    __shared__ __align__(16) float zs[256 * 16];
    int k0 = blockIdx.x * 256;
    for (int i = threadIdx.x; i < 4096; i += 256) {
        int b = i >> 8, kk = i & 255;
        zs[kk * 16 + b] = g_zq[b * SD_ + k0 + kk];
    }
    __syncthreads();

    int n = threadIdx.x;
    u64 acc[8];
#pragma unroll
    for (int b2 = 0; b2 < 8; ++b2) acc[b2] = 0ULL;

#pragma unroll 4
    for (int kk = 0; kk < 256; ++kk) {
        u64 wd = dupf(W[(size_t)(k0 + kk) * H2_ + n]);
        const ulonglong2* dk = (const ulonglong2*)(zs + kk * 16);
        ulonglong2 p0 = dk[0], p1 = dk[1], p2 = dk[2], p3 = dk[3];
        u64 dp[8] = {p0.x, p0.y, p1.x, p1.y, p2.x, p2.y, p3.x, p3.y};
#pragma unroll
        for (int b2 = 0; b2 < 8; ++b2) ffma2(acc[b2], dp[b2], wd);
    }
#pragma unroll
    for (int b2 = 0; b2 < 8; ++b2) {
        float2 f = unpk(acc[b2]);
        g_dpart[blockIdx.x * 4096 + (2*b2)   * H2_ + n] = f.x;
        g_dpart[blockIdx.x * 4096 + (2*b2+1) * H2_ + n] = f.y;
    }
}

__global__ void dec1_fin_kernel(const float* __restrict__ bias) {
    int n = blockIdx.x * 256 + threadIdx.x;
    float s = 0.0f;
    for (int c = 0; c < DEC1_CHUNKS; ++c) s += g_dpart[c * 4096 + n];
    g_dvec[n] = fmaxf(s + bias[n & 255], 0.0f);
}

__global__ void vqloss_kernel(float* __restrict__ out) {
    __shared__ float sb[256];
    float a = 0.0f;
    for (int i = threadIdx.x; i < T_; i += 256) a += g_tokloss[i];
    sb[threadIdx.x] = a;
    __syncthreads();
    for (int s = 128; s > 0; s >>= 1) {
        if (threadIdx.x < s) sb[threadIdx.x] += sb[threadIdx.x + s];
        __syncthreads();
    }
    if (threadIdx.x == 0) out[OUT_VQL] = sb[0] / (float)(T_ * D_);
}

__global__ __launch_bounds__(256, 2) void dec2_kernel(
    const float* __restrict__ W, const float* __restrict__ bias,
    float* __restrict__ out)
{
    __shared__ __align__(16) float ds[H2_ * 16];
    for (int i = threadIdx.x; i < 4096; i += 256) {
        int b = i >> 8, k = i & 255;
        ds[k * 16 + b] = g_dvec[i];
    }
    __syncthreads();

    int n = (blockIdx.x * 256 + threadIdx.x) * 4;
    if (n >= SF_) return;

    u64 acc[8][4];
#pragma unroll
    for (int b2 = 0; b2 < 8; ++b2)
#pragma unroll
        for (int c = 0; c < 4; ++c) acc[b2][c] = 0ULL;

#pragma unroll 4
    for (int k = 0; k < H2_; ++k) {
        float4 w = *(const float4*)(W + (size_t)k * SF_ + n);
        u64 wd[4] = {dupf(w.x), dupf(w.y), dupf(w.z), dupf(w.w)};
        const ulonglong2* dk = (const ulonglong2*)(ds + k * 16);
        ulonglong2 p0 = dk[0], p1 = dk[1], p2 = dk[2], p3 = dk[3];
        u64 dp[8] = {p0.x, p0.y, p1.x, p1.y, p2.x, p2.y, p3.x, p3.y};
#pragma unroll
        for (int b2 = 0; b2 < 8; ++b2)
#pragma unroll
            for (int c = 0; c < 4; ++c)
                ffma2(acc[b2][c], dp[b2], wd[c]);
    }

    float4 bb = *(const float4*)(bias + n);
#pragma unroll
    for (int b2 = 0; b2 < 8; ++b2) {
        float2 f0 = unpk(acc[b2][0]);
        float2 f1 = unpk(acc[b2][1]);
        float2 f2 = unpk(acc[b2][2]);
        float2 f3 = unpk(acc[b2][3]);
        float4 v0, v1;
        v0.x = softplusf(f0.x + bb.x);
        v0.y = softplusf(f1.x + bb.y);
        v0.z = softplusf(f2.x + bb.z);
        v0.w = softplusf(f3.x + bb.w);
        v1.x = softplusf(f0.y + bb.x);
        v1.y = softplusf(f1.y + bb.y);
        v1.z = softplusf(f2.y + bb.z);
        v1.w = softplusf(f3.y + bb.w);
        *(float4*)(out + (size_t)(2*b2)   * SF_ + n) = v0;
        *(float4*)(out + (size_t)(2*b2+1) * SF_ + n) = v1;
    }
}

// ---------------- launch ----------------
#define SYM(var) ({ void* _p; cudaGetSymbolAddress(&_p, var); _p; })

extern "C" void kernel_launch(void* const* d_in, const int* in_sizes, int n_in,
                              void* d_out, int out_size)
{
    const float* x   = (const float*)d_in[0];
    const float* eps = (const float*)d_in[1];
    const float* We1 = (const float*)d_in[2];
    const float* be1 = (const float*)d_in[3];
    const float* We2 = (const float*)d_in[4];
    const float* be2 = (const float*)d_in[5];
    const float* We3 = (const float*)d_in[6];
    const float* be3 = (const float*)d_in[7];
    const float* cb  = (const float*)d_in[8];
    const float* Wd1 = (const float*)d_in[9];
    const float* bd1 = (const float*)d_in[10];
    const float* Wd2 = (const float*)d_in[11];
    const float* bd2 = (const float*)d_in[12];
    float* out = (float*)d_out;

    bf16 *xh  = (bf16*)SYM(g_xh),  *xl  = (bf16*)SYM(g_xl);
    bf16 *w1h = (bf16*)SYM(g_w1h), *w1l = (bf16*)SYM(g_w1l);
    bf16 *w2h = (bf16*)SYM(g_w2h), *w2l = (bf16*)SYM(g_w2l);
    bf16 *w3h = (bf16*)SYM(g_w3h), *w3l = (bf16*)SYM(g_w3l);
    bf16 *h1h = (bf16*)SYM(g_h1h), *h1l = (bf16*)SYM(g_h1l);
    bf16 *h2h = (bf16*)SYM(g_h2h), *h2l = (bf16*)SYM(g_h2l);
    bf16 *zeh = (bf16*)SYM(g_zeh), *zel = (bf16*)SYM(g_zel);
    bf16 *cbh = (bf16*)SYM(g_cbh), *cbl = (bf16*)SYM(g_cbl);
    float *encp  = (float*)SYM(g_encp);
    float *cross = (float*)SYM(g_cross);

    cudaFuncSetAttribute(mma_gemm_bf<1>, cudaFuncAttributeMaxDynamicSharedMemorySize, SMEM_BYTES);
    cudaFuncSetAttribute(mma_gemm_bf<2>, cudaFuncAttributeMaxDynamicSharedMemorySize, SMEM_BYTES);
    cudaFuncSetAttribute(mma_gemm_bf<3>, cudaFuncAttributeMaxDynamicSharedMemorySize, SMEM_BYTES);

    // pre-split operands
    split_x_kernel<<<(T_ * (FP_/4) + 255) / 256, 256>>>(x);
    transpose_split_kernel<<<dim3(16, 22), dim3(32, 8)>>>(We1, w1h, w1l, F_,  H1_, FP_);
    transpose_split_kernel<<<dim3(8, 16),  dim3(32, 8)>>>(We2, w2h, w2l, H1_, H2_, H1_);
    transpose_split_kernel<<<dim3(4, 8),   dim3(32, 8)>>>(We3, w3h, w3l, H2_, ENC_, H2_);
    cb_prep_kernel<<<128, 256>>>(cb);

    // encoder MLP on tensor cores (bf16x3, pre-split)
    mma_gemm_bf<1><<<dim3(4, 72), 256, SMEM_BYTES>>>(T_, H1_, FP_, 0,
        xh, xl, w1h, w1l, be1, nullptr, h1h, h1l);
    mma_gemm_bf<1><<<dim3(2, 72), 256, SMEM_BYTES>>>(T_, H2_, H1_, 0,
        h1h, h1l, w2h, w2l, be2, nullptr, h2h, h2l);
    mma_gemm_bf<2><<<dim3(1, 72, ZSPLIT), 256, SMEM_BYTES>>>(T_, ENC_, H2_, H2_/ZSPLIT,
        h2h, h2l, w3h, w3l, nullptr, encp, nullptr, nullptr);

    reparam_kernel<<<(T_ * D_ + 255) / 256, 256>>>(eps, be3, out);

    // VQ cross = z_e @ codebook^T
    mma_gemm_bf<3><<<dim3(8, 72), 256, SMEM_BYTES>>>(T_, KC_, D_, 0,
        zeh, zel, cbh, cbl, nullptr, cross, nullptr, nullptr);
    argmin_kernel<<<T_ / 8, 256>>>(cb);

    // decoder
    dec1_part_kernel<<<DEC1_CHUNKS, 256>>>(Wd1);
    dec1_fin_kernel<<<16, 256>>>(bd1);
    vqloss_kernel<<<1, 256>>>(out);
    dec2_kernel<<<(SF_ / 4 + 255) / 256, 256>>>(Wd2, bd2, out);
}